// round 2
// baseline (speedup 1.0000x reference)
#include <cuda_runtime.h>

#define TB      32      // batch elements per CTA
#define THREADS 384     // 3 agents x 128 hidden channels

// smem float offsets
#define OFF_IN    0                  // [3][TB][40]   obs(30)+act(9)+pad
#define OFF_OEMB  (3*TB*40)          // [3][TB][128]  o_emb (persists)
#define OFF_OA    (OFF_OEMB + 3*TB*128) // [3][TB][128] oa_emb, reused as attn_out
#define OFF_K     (OFF_OA   + 3*TB*128) // [3][TB][128] K, reused as h1
#define OFF_V     (OFF_K    + 3*TB*128) // [3][TB][128] V
#define SMEM_FLOATS (OFF_V + 3*TB*128)

__global__ __launch_bounds__(THREADS, 1)
void valuenet_kernel(
    const float* __restrict__ obs,  const float* __restrict__ act,
    const float* __restrict__ W_o,  const float* __restrict__ b_o,
    const float* __restrict__ W_oa, const float* __restrict__ b_oa,
    const float* __restrict__ Wq,   const float* __restrict__ bq,
    const float* __restrict__ Wk,   const float* __restrict__ bk,
    const float* __restrict__ Wv,   const float* __restrict__ bv,
    const float* __restrict__ Wc1,  const float* __restrict__ bc1,
    const float* __restrict__ Wc2,  const float* __restrict__ bc2,
    float* __restrict__ out)
{
    extern __shared__ float sm[];
    float* s_in   = sm + OFF_IN;
    float* s_oemb = sm + OFF_OEMB;
    float* s_oa   = sm + OFF_OA;   // oa_emb, later attn_out
    float* s_K    = sm + OFF_K;    // K, later h1
    float* s_V    = sm + OFF_V;

    const int t  = threadIdx.x;
    const int n  = t >> 7;         // agent 0..2
    const int h  = t & 127;        // hidden channel 0..127
    const int e0 = blockIdx.x * TB;

    // ---------------- P0: stage inputs ----------------
    for (int i = t; i < TB * 90; i += THREADS) {
        int e = i / 90, r = i - e * 90;
        int nn = r / 30, d = r - nn * 30;
        s_in[(nn * TB + e) * 40 + d] = obs[(long)(e0 + e) * 90 + r];
    }
    for (int i = t; i < TB * 27; i += THREADS) {
        int e = i / 27, r = i - e * 27;
        int nn = r / 9, d = r - nn * 9;
        s_in[(nn * TB + e) * 40 + 30 + d] = act[(long)(e0 + e) * 27 + r];
    }
    __syncthreads();

    // ---------------- P1: per-agent embeds ----------------
    {
        float w[39];
        float acc[TB];

        // o_emb = leaky(obs @ W_o[n] + b_o[n])
        #pragma unroll
        for (int d = 0; d < 30; d++) w[d] = W_o[(n * 30 + d) * 128 + h];
        float bias = b_o[n * 128 + h];
        #pragma unroll
        for (int e = 0; e < TB; e++) acc[e] = bias;
        #pragma unroll
        for (int d = 0; d < 30; d++) {
            float wd = w[d];
            #pragma unroll
            for (int e = 0; e < TB; e++)
                acc[e] += s_in[(n * TB + e) * 40 + d] * wd;
        }
        #pragma unroll
        for (int e = 0; e < TB; e++) {
            float v = acc[e];
            s_oemb[(n * TB + e) * 128 + h] = (v >= 0.f) ? v : 0.01f * v;
        }

        // oa_emb = leaky([obs,act] @ W_oa[n] + b_oa[n])
        #pragma unroll
        for (int d = 0; d < 39; d++) w[d] = W_oa[(n * 39 + d) * 128 + h];
        bias = b_oa[n * 128 + h];
        #pragma unroll
        for (int e = 0; e < TB; e++) acc[e] = bias;
        #pragma unroll
        for (int d = 0; d < 39; d++) {
            float wd = w[d];
            #pragma unroll
            for (int e = 0; e < TB; e++)
                acc[e] += s_in[(n * TB + e) * 40 + d] * wd;
        }
        #pragma unroll
        for (int e = 0; e < TB; e++) {
            float v = acc[e];
            s_oa[(n * TB + e) * 128 + h] = (v >= 0.f) ? v : 0.01f * v;
        }
    }
    __syncthreads();

    // ---------------- P2: Q/K/V projections ----------------
    float qacc[TB];   // Q stays in registers through attention
    {
        float bias = bq[h];
        #pragma unroll
        for (int e = 0; e < TB; e++) qacc[e] = bias;
        #pragma unroll 4
        for (int k = 0; k < 128; k++) {
            float w = Wq[k * 128 + h];
            #pragma unroll
            for (int e = 0; e < TB; e++)
                qacc[e] += s_oemb[(n * TB + e) * 128 + k] * w;
        }
    }
    {
        float tacc[TB];
        float bias = bk[h];
        #pragma unroll
        for (int e = 0; e < TB; e++) tacc[e] = bias;
        #pragma unroll 4
        for (int k = 0; k < 128; k++) {
            float w = Wk[k * 128 + h];
            #pragma unroll
            for (int e = 0; e < TB; e++)
                tacc[e] += s_oa[(n * TB + e) * 128 + k] * w;
        }
        #pragma unroll
        for (int e = 0; e < TB; e++) s_K[(n * TB + e) * 128 + h] = tacc[e];

        bias = bv[h];
        #pragma unroll
        for (int e = 0; e < TB; e++) tacc[e] = bias;
        #pragma unroll 4
        for (int k = 0; k < 128; k++) {
            float w = Wv[k * 128 + h];
            #pragma unroll
            for (int e = 0; e < TB; e++)
                tacc[e] += s_oa[(n * TB + e) * 128 + k] * w;
        }
        #pragma unroll
        for (int e = 0; e < TB; e++) s_V[(n * TB + e) * 128 + h] = tacc[e];
    }
    __syncthreads();

    // ---------------- P3: 3-agent masked attention ----------------
    // warp == (agent n, head h/32); lanes span the 32 dims of this head.
    {
        const float scale = 0.17677669529663689f;  // 1/sqrt(32)
        #pragma unroll 1
        for (int e = 0; e < TB; e++) {
            float q  = qacc[e];
            float s0 = q * s_K[(0 * TB + e) * 128 + h];
            float s1 = q * s_K[(1 * TB + e) * 128 + h];
            float s2 = q * s_K[(2 * TB + e) * 128 + h];
            #pragma unroll
            for (int off = 16; off > 0; off >>= 1) {
                s0 += __shfl_xor_sync(0xffffffffu, s0, off);
                s1 += __shfl_xor_sync(0xffffffffu, s1, off);
                s2 += __shfl_xor_sync(0xffffffffu, s2, off);
            }
            s0 *= scale; s1 *= scale; s2 *= scale;
            if (n == 0)      s0 -= 1e10f;   // diag mask
            else if (n == 1) s1 -= 1e10f;
            else             s2 -= 1e10f;
            float mx  = fmaxf(s0, fmaxf(s1, s2));
            float p0  = expf(s0 - mx);
            float p1  = expf(s1 - mx);
            float p2  = expf(s2 - mx);
            float inv = 1.0f / (p0 + p1 + p2);
            float ao = (p0 * s_V[(0 * TB + e) * 128 + h]
                      + p1 * s_V[(1 * TB + e) * 128 + h]
                      + p2 * s_V[(2 * TB + e) * 128 + h]) * inv;
            s_oa[(n * TB + e) * 128 + h] = ao;   // attn_out overwrites oa_emb
        }
    }
    __syncthreads();

    // ---------------- P4: critic layer 1 (256 -> 128) ----------------
    {
        float hacc[TB];
        float bias = bc1[n * 128 + h];
        #pragma unroll
        for (int e = 0; e < TB; e++) hacc[e] = bias;
        #pragma unroll 4
        for (int k = 0; k < 128; k++) {
            float w = Wc1[(n * 256 + k) * 128 + h];
            #pragma unroll
            for (int e = 0; e < TB; e++)
                hacc[e] += s_oemb[(n * TB + e) * 128 + k] * w;
        }
        #pragma unroll 4
        for (int k = 0; k < 128; k++) {
            float w = Wc1[(n * 256 + 128 + k) * 128 + h];
            #pragma unroll
            for (int e = 0; e < TB; e++)
                hacc[e] += s_oa[(n * TB + e) * 128 + k] * w;
        }
        #pragma unroll
        for (int e = 0; e < TB; e++) {
            float v = hacc[e];
            s_K[(n * TB + e) * 128 + h] = (v >= 0.f) ? v : 0.01f * v;  // h1 reuses K
        }
    }
    __syncthreads();

    // ---------------- P5: critic layer 2 (128 -> 9) + store ----------------
    for (int idx = t; idx < TB * 27; idx += THREADS) {
        int e = idx / 27, r = idx - e * 27;
        int nn = r / 9,  a = r - nn * 9;
        float acc = bc2[nn * 9 + a];
        #pragma unroll 4
        for (int j = 0; j < 128; j++)
            acc += s_K[(nn * TB + e) * 128 + j] * Wc2[(nn * 128 + j) * 9 + a];
        out[(long)(e0 + e) * 27 + r] = acc;
    }
}

extern "C" void kernel_launch(void* const* d_in, const int* in_sizes, int n_in,
                              void* d_out, int out_size) {
    const float* obs  = (const float*)d_in[0];
    const float* act  = (const float*)d_in[1];
    const float* W_o  = (const float*)d_in[2];
    const float* b_o  = (const float*)d_in[3];
    const float* W_oa = (const float*)d_in[4];
    const float* b_oa = (const float*)d_in[5];
    const float* Wq   = (const float*)d_in[6];
    const float* bq   = (const float*)d_in[7];
    const float* Wk   = (const float*)d_in[8];
    const float* bk   = (const float*)d_in[9];
    const float* Wv   = (const float*)d_in[10];
    const float* bv   = (const float*)d_in[11];
    const float* Wc1  = (const float*)d_in[12];
    const float* bc1  = (const float*)d_in[13];
    const float* Wc2  = (const float*)d_in[14];
    const float* bc2  = (const float*)d_in[15];
    float* out = (float*)d_out;

    const int batch = in_sizes[0] / (3 * 30);   // 131072
    const int grid  = batch / TB;
    const size_t smem = SMEM_FLOATS * sizeof(float);  // ~207 KB

    cudaFuncSetAttribute(valuenet_kernel,
                         cudaFuncAttributeMaxDynamicSharedMemorySize, (int)smem);
    valuenet_kernel<<<grid, THREADS, smem>>>(
        obs, act, W_o, b_o, W_oa, b_oa, Wq, bq, Wk, bk, Wv, bv,
        Wc1, bc1, Wc2, bc2, out);
}

// round 7
// speedup vs baseline: 1.6036x; 1.6036x over previous
#include <cuda_runtime.h>

#define TB      16      // batch elements per CTA
#define THREADS 384     // 3 agents x 64 h-pairs x 2 e-halves (8 e each)

// smem float offsets
#define OFF_IN    0                     // [3][TB][40]  obs(30)+act(9)+pad
#define OFF_OEMB  (3*TB*40)             // [3][TB][128] o_emb (persists)
#define OFF_OA    (OFF_OEMB + 3*TB*128) // [3][TB][128] oa_emb, reused as attn_out
#define OFF_K     (OFF_OA   + 3*TB*128) // [3][TB][128] K, reused as h1
#define OFF_V     (OFF_K    + 3*TB*128) // [3][TB][128] V
#define SMEM_FLOATS (OFF_V + 3*TB*128)  // 26496 floats = 103.5 KB

// acc0/acc1[e] += sum_k in[e][k] * W[k*128 + (h0 / h0+1)]
// sp: smem pointer to in[e=0][k=0]; ESTRIDE floats between e rows.
// Weights treated as zero for k >= KVALID (input rows are padded/valid there).
// All smem loads are warp-uniform float4 broadcasts (1 wavefront each).
template<int NQ, int KVALID, int ESTRIDE>
__device__ __forceinline__ void gemm8s(const float* __restrict__ sp,
                                       const float* __restrict__ Wp,
                                       float acc0[8], float acc1[8])
{
    #pragma unroll
    for (int q = 0; q < NQ; q++) {
        const int k = q * 4;
        const float2 z = make_float2(0.f, 0.f);
        float2 w0 = (k+0 < KVALID) ? *(const float2*)(Wp + (k+0)*128) : z;
        float2 w1 = (k+1 < KVALID) ? *(const float2*)(Wp + (k+1)*128) : z;
        float2 w2 = (k+2 < KVALID) ? *(const float2*)(Wp + (k+2)*128) : z;
        float2 w3 = (k+3 < KVALID) ? *(const float2*)(Wp + (k+3)*128) : z;
        #pragma unroll
        for (int e = 0; e < 8; e++) {
            const float4 x = *(const float4*)(sp + e*ESTRIDE + k);
            float a0 = acc0[e], a1 = acc1[e];
            a0 = fmaf(x.x, w0.x, a0); a1 = fmaf(x.x, w0.y, a1);
            a0 = fmaf(x.y, w1.x, a0); a1 = fmaf(x.y, w1.y, a1);
            a0 = fmaf(x.z, w2.x, a0); a1 = fmaf(x.z, w2.y, a1);
            a0 = fmaf(x.w, w3.x, a0); a1 = fmaf(x.w, w3.y, a1);
            acc0[e] = a0; acc1[e] = a1;
        }
    }
}

__global__ __launch_bounds__(THREADS, 2)
void valuenet_kernel(
    const float* __restrict__ obs,  const float* __restrict__ act,
    const float* __restrict__ W_o,  const float* __restrict__ b_o,
    const float* __restrict__ W_oa, const float* __restrict__ b_oa,
    const float* __restrict__ Wq,   const float* __restrict__ bq,
    const float* __restrict__ Wk,   const float* __restrict__ bk,
    const float* __restrict__ Wv,   const float* __restrict__ bv,
    const float* __restrict__ Wc1,  const float* __restrict__ bc1,
    const float* __restrict__ Wc2,  const float* __restrict__ bc2,
    float* __restrict__ out)
{
    extern __shared__ float sm[];
    float* s_in   = sm + OFF_IN;
    float* s_oemb = sm + OFF_OEMB;
    float* s_oa   = sm + OFF_OA;   // oa_emb, later attn_out
    float* s_K    = sm + OFF_K;    // K, later h1
    float* s_V    = sm + OFF_V;

    const int t   = threadIdx.x;
    const int n   = t >> 7;        // agent 0..2
    const int r   = t & 127;
    const int h2  = r & 63;        // h-pair index
    const int eh  = r >> 6;        // e-half 0/1 (uniform per warp)
    const int h0  = h2 * 2;        // first owned channel
    const int eb  = eh * 8;        // first of the 8 owned e's
    const int e0g = blockIdx.x * TB;

    // ---------------- P0: stage inputs ----------------
    for (int i = t; i < TB * 90; i += THREADS) {
        int e = i / 90, rr = i - e * 90;
        int nn = rr / 30, d = rr - nn * 30;
        s_in[(nn * TB + e) * 40 + d] = obs[(long)(e0g + e) * 90 + rr];
    }
    for (int i = t; i < TB * 27; i += THREADS) {
        int e = i / 27, rr = i - e * 27;
        int nn = rr / 9, d = rr - nn * 9;
        s_in[(nn * TB + e) * 40 + 30 + d] = act[(long)(e0g + e) * 27 + rr];
    }
    if (t < 3 * TB) s_in[t * 40 + 39] = 0.f;  // pad col
    __syncthreads();

    // ---------------- P1: per-agent embeds ----------------
    {
        const float* sp = s_in + (n * TB + eb) * 40;
        {
            float a0[8], a1[8];
            float b0 = b_o[n*128 + h0], b1 = b_o[n*128 + h0 + 1];
            #pragma unroll
            for (int e = 0; e < 8; e++) { a0[e] = b0; a1[e] = b1; }
            gemm8s<8, 30, 40>(sp, W_o + n * 30 * 128 + h0, a0, a1);
            #pragma unroll
            for (int e = 0; e < 8; e++) {
                float v0 = a0[e], v1 = a1[e];
                v0 = (v0 >= 0.f) ? v0 : 0.01f * v0;
                v1 = (v1 >= 0.f) ? v1 : 0.01f * v1;
                *(float2*)&s_oemb[(n*TB + eb + e)*128 + h0] = make_float2(v0, v1);
            }
        }
        {
            float a0[8], a1[8];
            float b0 = b_oa[n*128 + h0], b1 = b_oa[n*128 + h0 + 1];
            #pragma unroll
            for (int e = 0; e < 8; e++) { a0[e] = b0; a1[e] = b1; }
            gemm8s<10, 39, 40>(sp, W_oa + n * 39 * 128 + h0, a0, a1);
            #pragma unroll
            for (int e = 0; e < 8; e++) {
                float v0 = a0[e], v1 = a1[e];
                v0 = (v0 >= 0.f) ? v0 : 0.01f * v0;
                v1 = (v1 >= 0.f) ? v1 : 0.01f * v1;
                *(float2*)&s_oa[(n*TB + eb + e)*128 + h0] = make_float2(v0, v1);
            }
        }
    }
    __syncthreads();

    // ---------------- P2: Q/K/V projections ----------------
    float q0[8], q1[8];   // Q stays in registers (static-indexed everywhere)
    {
        const float* spQ = s_oemb + (n * TB + eb) * 128;
        const float* spA = s_oa   + (n * TB + eb) * 128;
        {   // Q
            float b0 = bq[h0], b1 = bq[h0 + 1];
            #pragma unroll
            for (int e = 0; e < 8; e++) { q0[e] = b0; q1[e] = b1; }
            gemm8s<32, 128, 128>(spQ, Wq + h0, q0, q1);
        }
        {   // K
            float a0[8], a1[8];
            float b0 = bk[h0], b1 = bk[h0 + 1];
            #pragma unroll
            for (int e = 0; e < 8; e++) { a0[e] = b0; a1[e] = b1; }
            gemm8s<32, 128, 128>(spA, Wk + h0, a0, a1);
            #pragma unroll
            for (int e = 0; e < 8; e++)
                *(float2*)&s_K[(n*TB + eb + e)*128 + h0] = make_float2(a0[e], a1[e]);
        }
        {   // V
            float a0[8], a1[8];
            float b0 = bv[h0], b1 = bv[h0 + 1];
            #pragma unroll
            for (int e = 0; e < 8; e++) { a0[e] = b0; a1[e] = b1; }
            gemm8s<32, 128, 128>(spA, Wv + h0, a0, a1);
            #pragma unroll
            for (int e = 0; e < 8; e++)
                *(float2*)&s_V[(n*TB + eb + e)*128 + h0] = make_float2(a0[e], a1[e]);
        }
    }
    __syncthreads();

    // ---------------- P3: 3-agent masked attention ----------------
    // 16 lanes x 2 dims = one 32-dim head; xor-shuffle reduce within 16 lanes.
    // Fully unrolled; q0/q1 static-indexed.
    {
        const float scale = 0.17677669529663689f;  // 1/sqrt(32)
        #pragma unroll
        for (int ei = 0; ei < 8; ei++) {
            const int e = eb + ei;
            float2 k0 = *(float2*)&s_K[(0*TB + e)*128 + h0];
            float2 k1 = *(float2*)&s_K[(1*TB + e)*128 + h0];
            float2 k2 = *(float2*)&s_K[(2*TB + e)*128 + h0];
            float s0 = q0[ei]*k0.x + q1[ei]*k0.y;
            float s1 = q0[ei]*k1.x + q1[ei]*k1.y;
            float s2 = q0[ei]*k2.x + q1[ei]*k2.y;
            #pragma unroll
            for (int off = 8; off > 0; off >>= 1) {
                s0 += __shfl_xor_sync(0xffffffffu, s0, off);
                s1 += __shfl_xor_sync(0xffffffffu, s1, off);
                s2 += __shfl_xor_sync(0xffffffffu, s2, off);
            }
            s0 *= scale; s1 *= scale; s2 *= scale;
            if (n == 0)      s0 -= 1e10f;
            else if (n == 1) s1 -= 1e10f;
            else             s2 -= 1e10f;
            float mx  = fmaxf(s0, fmaxf(s1, s2));
            float p0  = __expf(s0 - mx);
            float p1  = __expf(s1 - mx);
            float p2  = __expf(s2 - mx);
            float inv = 1.0f / (p0 + p1 + p2);
            float2 v0 = *(float2*)&s_V[(0*TB + e)*128 + h0];
            float2 v1 = *(float2*)&s_V[(1*TB + e)*128 + h0];
            float2 v2 = *(float2*)&s_V[(2*TB + e)*128 + h0];
            float ax = (p0*v0.x + p1*v1.x + p2*v2.x) * inv;
            float ay = (p0*v0.y + p1*v1.y + p2*v2.y) * inv;
            *(float2*)&s_oa[(n*TB + e)*128 + h0] = make_float2(ax, ay);  // attn_out
        }
    }
    __syncthreads();

    // ---------------- P4: critic layer 1 (256 -> 128) ----------------
    {
        float a0[8], a1[8];
        float b0 = bc1[n*128 + h0], b1 = bc1[n*128 + h0 + 1];
        #pragma unroll
        for (int e = 0; e < 8; e++) { a0[e] = b0; a1[e] = b1; }
        gemm8s<32, 128, 128>(s_oemb + (n*TB + eb) * 128,
                             Wc1 + (size_t)n * 256 * 128 + h0, a0, a1);
        gemm8s<32, 128, 128>(s_oa + (n*TB + eb) * 128,
                             Wc1 + ((size_t)n * 256 + 128) * 128 + h0, a0, a1);
        #pragma unroll
        for (int e = 0; e < 8; e++) {
            float v0 = a0[e], v1 = a1[e];
            v0 = (v0 >= 0.f) ? v0 : 0.01f * v0;
            v1 = (v1 >= 0.f) ? v1 : 0.01f * v1;
            *(float2*)&s_K[(n*TB + eb + e)*128 + h0] = make_float2(v0, v1);  // h1
        }
    }
    __syncthreads();

    // ---------------- P5: critic layer 2 (128 -> 9) + store ----------------
    for (int idx = t; idx < TB * 27; idx += THREADS) {
        int e = idx / 27, rr = idx - e * 27;
        int nn = rr / 9,  a = rr - nn * 9;
        float acc = bc2[nn * 9 + a];
        const float* hp = &s_K[(nn * TB + e) * 128];
        const float* wp = Wc2 + (size_t)nn * 128 * 9 + a;
        #pragma unroll 8
        for (int j = 0; j < 128; j += 4) {
            float4 x = *(const float4*)(hp + j);
            acc += x.x * wp[(j+0)*9] + x.y * wp[(j+1)*9]
                 + x.z * wp[(j+2)*9] + x.w * wp[(j+3)*9];
        }
        out[(long)(e0g + e) * 27 + rr] = acc;
    }
}

extern "C" void kernel_launch(void* const* d_in, const int* in_sizes, int n_in,
                              void* d_out, int out_size) {
    const float* obs  = (const float*)d_in[0];
    const float* act  = (const float*)d_in[1];
    const float* W_o  = (const float*)d_in[2];
    const float* b_o  = (const float*)d_in[3];
    const float* W_oa = (const float*)d_in[4];
    const float* b_oa = (const float*)d_in[5];
    const float* Wq   = (const float*)d_in[6];
    const float* bq   = (const float*)d_in[7];
    const float* Wk   = (const float*)d_in[8];
    const float* bk   = (const float*)d_in[9];
    const float* Wv   = (const float*)d_in[10];
    const float* bv   = (const float*)d_in[11];
    const float* Wc1  = (const float*)d_in[12];
    const float* bc1  = (const float*)d_in[13];
    const float* Wc2  = (const float*)d_in[14];
    const float* bc2  = (const float*)d_in[15];
    float* out = (float*)d_out;

    const int batch = in_sizes[0] / (3 * 30);   // 131072
    const int grid  = batch / TB;               // 8192
    const size_t smem = SMEM_FLOATS * sizeof(float);  // 103.5 KB

    cudaFuncSetAttribute(valuenet_kernel,
                         cudaFuncAttributeMaxDynamicSharedMemorySize, (int)smem);
    valuenet_kernel<<<grid, THREADS, smem>>>(
        obs, act, W_o, b_o, W_oa, b_oa, Wq, bq, Wk, bk, Wv, bv,
        Wc1, bc1, Wc2, bc2, out);
}